// round 8
// baseline (speedup 1.0000x reference)
#include <cuda_runtime.h>
#include <cuda_bf16.h>
#include <cstddef>

// Sorted segment-sum: feat[1e6, 128] fp32 -> out[4096, 128] fp32.
// PERSISTENT single-wave grid (592 blocks = 148 SMs x 4 resident, 8 warps)
// with SHARDED dynamic work-stealing. R6 lesson: one global ticket counter
// saturates the per-address L2 atomic ALU (1.2 req/cyc demand vs <1/cyc
// service) -> queue starvation. Fix: 16 ticket counters, 128B apart
// (distinct L2 slices), one per group of 37 blocks (296 warps). Each group
// owns a contiguous 1/16 of 47360 globally-balanced chains (2960 chains,
// equal tiles per group by construction) -> per-counter demand ~0.07
// req/cyc, fully served; next-ticket prefetch hides the 318cyc latency.
// Hot loop: 8 rows/iter, branch-free front-batched streaming loads
// (2x int4 seg + 8x float4 feat => MLP ~10/warp). Sortedness: last id in
// batch == cur => whole batch == cur. Flushes are atomicAdds into the 2MB
// L2-resident output.

#define WARPS_PER_BLOCK 8
#define THREADS (WARPS_PER_BLOCK * 32)
#define GRID_BLOCKS 592                 // one resident wave
#define N_GROUPS 16                     // 592 % 16 == 0 -> 37 blocks/group
#define CHAINS_PER_GROUP 2960
#define N_CHAINS (N_GROUPS * CHAINS_PER_GROUP)   // 47360 (~10 per warp)
#define D_FEAT 128

__device__ unsigned int g_tickets[N_GROUPS * 32];   // 128B stride per counter

__global__ void zero_out_kernel(float4* __restrict__ out, int n4) {
    int i = blockIdx.x * blockDim.x + threadIdx.x;
    if (i < N_GROUPS) g_tickets[i * 32] = 0u;   // reset counters each replay
    if (i < n4) out[i] = make_float4(0.f, 0.f, 0.f, 0.f);
}

__device__ __forceinline__ float4 f4add(float4 a, float4 b) {
    return make_float4(a.x + b.x, a.y + b.y, a.z + b.z, a.w + b.w);
}

__device__ __forceinline__ void flush_acc(float* __restrict__ out, int cur,
                                          int lane, float4 acc) {
    float* dst = out + (size_t)cur * D_FEAT + lane * 4;
    atomicAdd(dst + 0, acc.x);
    atomicAdd(dst + 1, acc.y);
    atomicAdd(dst + 2, acc.z);
    atomicAdd(dst + 3, acc.w);
}

__device__ __forceinline__ unsigned int warp_ticket(unsigned int* counter, int lane) {
    unsigned int t = 0;
    if (lane == 0) t = atomicAdd(counter, 1u);
    return __shfl_sync(0xffffffffu, t, 0);
}

__global__ __launch_bounds__(THREADS, 4)
void segsum_kernel(const float4* __restrict__ feat4,
                   const int* __restrict__ seg,
                   float* __restrict__ out,
                   int n_rows) {
    const int lane = threadIdx.x & 31;
    const int group = blockIdx.x & (N_GROUPS - 1);
    unsigned int* counter = &g_tickets[group * 32];
    const long chain_base = (long)group * CHAINS_PER_GROUP;
    const long n_tiles = n_rows >> 3;   // full 8-row tiles

    unsigned int t = warp_ticket(counter, lane);
    while (t < CHAINS_PER_GROUP) {
        // Prefetch next ticket; latency overlaps with this chain's work.
        unsigned int t_next = warp_ticket(counter, lane);
        const long chain = chain_base + t;

        // Globally balanced split: chain c owns tiles [c*T/N, (c+1)*T/N)
        long tt0 = (chain * n_tiles) / N_CHAINS;
        long tt1 = ((chain + 1) * n_tiles) / N_CHAINS;
        long r0 = tt0 << 3;
        long r1 = tt1 << 3;
        if (chain == N_CHAINS - 1) r1 = n_rows;   // remainder rows
        if (r0 >= r1) { t = t_next; continue; }

        float4 acc = make_float4(0.f, 0.f, 0.f, 0.f);
        int cur = __ldcs(seg + r0);

        long r = r0;
        // ---------- hot loop: branch-free loads, 8 rows / iter ----------
        for (; r + 8 <= r1; r += 8) {
            const int4 sA = __ldcs(reinterpret_cast<const int4*>(seg + r));
            const int4 sB = __ldcs(reinterpret_cast<const int4*>(seg + r + 4));
            const float4* base = feat4 + (size_t)r * (D_FEAT / 4) + lane;
            const float4 v0 = __ldcs(base + 0 * 32);
            const float4 v1 = __ldcs(base + 1 * 32);
            const float4 v2 = __ldcs(base + 2 * 32);
            const float4 v3 = __ldcs(base + 3 * 32);
            const float4 v4 = __ldcs(base + 4 * 32);
            const float4 v5 = __ldcs(base + 5 * 32);
            const float4 v6 = __ldcs(base + 6 * 32);
            const float4 v7 = __ldcs(base + 7 * 32);

            if (sB.w == cur) {
                // sorted ids: last == cur  =>  all 8 == cur
                float4 t0s = f4add(f4add(v0, v1), f4add(v2, v3));
                float4 t1s = f4add(f4add(v4, v5), f4add(v6, v7));
                acc = f4add(acc, f4add(t0s, t1s));
            } else {
                // cold path: segment boundary inside this batch
                int s[8] = {sA.x, sA.y, sA.z, sA.w, sB.x, sB.y, sB.z, sB.w};
                float4 v[8] = {v0, v1, v2, v3, v4, v5, v6, v7};
                #pragma unroll
                for (int i = 0; i < 8; i++) {
                    if (s[i] != cur) {
                        flush_acc(out, cur, lane, acc);
                        acc = make_float4(0.f, 0.f, 0.f, 0.f);
                        cur = s[i];
                    }
                    acc = f4add(acc, v[i]);
                }
            }
        }
        // ---------- scalar tail (only last chain, if n_rows % 8 != 0) ----------
        for (; r < r1; ++r) {
            int s = __ldcs(seg + r);
            float4 v = __ldcs(feat4 + (size_t)r * (D_FEAT / 4) + lane);
            if (s != cur) {
                flush_acc(out, cur, lane, acc);
                acc = make_float4(0.f, 0.f, 0.f, 0.f);
                cur = s;
            }
            acc = f4add(acc, v);
        }

        flush_acc(out, cur, lane, acc);
        t = t_next;
    }
}

extern "C" void kernel_launch(void* const* d_in, const int* in_sizes, int n_in,
                              void* d_out, int out_size) {
    const float* feat = (const float*)d_in[0];
    const int* seg = (const int*)d_in[1];
    float* out = (float*)d_out;

    const int n_rows = in_sizes[0] / D_FEAT;  // 1,000,000
    const int n4 = out_size / 4;              // 131072

    zero_out_kernel<<<(n4 + 255) / 256, 256>>>((float4*)out, n4);
    segsum_kernel<<<GRID_BLOCKS, THREADS>>>((const float4*)feat, seg, out, n_rows);
}

// round 9
// speedup vs baseline: 1.0603x; 1.0603x over previous
#include <cuda_runtime.h>
#include <cuda_bf16.h>
#include <cstddef>

// Sorted segment-sum: feat[1e6, 128] fp32 -> out[4096, 128] fp32.
// R3 architecture (best so far): static dispatch, 2368 blocks = 4 waves of
// 4 resident blocks/SM, one warp per contiguous chain of 8-row tiles,
// balanced split. NEW in R9: GUIDED two-tier chain sizing - blocks execute
// roughly in index order, so the first 3 waves (14208 chains) take 7/8 of
// the tiles (~61-row chains) and the LAST wave (4736 chains) takes 1/8
// (~26-row chains). The final wave is the only one whose completion spread
// is exposed as chip idle; 2.4x shorter chains shrink that tail ~2.4x.
// Hot loop: 8 rows/iter, branch-free front-batched streaming loads
// (2x int4 seg + 8x float4 feat => MLP ~10/warp). Sortedness: last id in
// batch == cur => whole batch == cur. Flushes are atomicAdds into the 2MB
// L2-resident output - negligible DRAM traffic.

#define WARPS_PER_BLOCK 8
#define THREADS (WARPS_PER_BLOCK * 32)
#define GRID_BLOCKS 2368                        // 4 waves x 592
#define N_CHAINS ((long)GRID_BLOCKS * WARPS_PER_BLOCK)  // 18944
#define T1_CHAINS 14208                         // first 3 waves
#define T2_CHAINS 4736                          // last wave
#define D_FEAT 128

__global__ void zero_out_kernel(float4* __restrict__ out, int n4) {
    int i = blockIdx.x * blockDim.x + threadIdx.x;
    if (i < n4) out[i] = make_float4(0.f, 0.f, 0.f, 0.f);
}

__device__ __forceinline__ float4 f4add(float4 a, float4 b) {
    return make_float4(a.x + b.x, a.y + b.y, a.z + b.z, a.w + b.w);
}

__device__ __forceinline__ void flush_acc(float* __restrict__ out, int cur,
                                          int lane, float4 acc) {
    float* dst = out + (size_t)cur * D_FEAT + lane * 4;
    atomicAdd(dst + 0, acc.x);
    atomicAdd(dst + 1, acc.y);
    atomicAdd(dst + 2, acc.z);
    atomicAdd(dst + 3, acc.w);
}

__global__ __launch_bounds__(THREADS, 4)
void segsum_kernel(const float4* __restrict__ feat4,
                   const int* __restrict__ seg,
                   float* __restrict__ out,
                   int n_rows) {
    const int warp = threadIdx.x >> 5;
    const int lane = threadIdx.x & 31;
    const long chain = (long)blockIdx.x * WARPS_PER_BLOCK + warp;

    const long n_tiles = n_rows >> 3;            // full 8-row tiles
    const long tiles_t1 = (n_tiles * 7) >> 3;    // 7/8 to the first 3 waves

    // Guided two-tier balanced split.
    long t0, t1;
    if (chain < T1_CHAINS) {
        t0 = (chain * tiles_t1) / T1_CHAINS;
        t1 = ((chain + 1) * tiles_t1) / T1_CHAINS;
    } else {
        const long c2 = chain - T1_CHAINS;
        const long tiles_t2 = n_tiles - tiles_t1;
        t0 = tiles_t1 + (c2 * tiles_t2) / T2_CHAINS;
        t1 = tiles_t1 + ((c2 + 1) * tiles_t2) / T2_CHAINS;
    }
    long r0 = t0 << 3;
    long r1 = t1 << 3;
    if (chain == N_CHAINS - 1) r1 = n_rows;      // remainder rows
    if (r0 >= r1) return;

    float4 acc = make_float4(0.f, 0.f, 0.f, 0.f);
    int cur = __ldcs(seg + r0);

    long r = r0;
    // ---------- hot loop: branch-free loads, 8 rows / iter ----------
    for (; r + 8 <= r1; r += 8) {
        const int4 sA = __ldcs(reinterpret_cast<const int4*>(seg + r));
        const int4 sB = __ldcs(reinterpret_cast<const int4*>(seg + r + 4));
        const float4* base = feat4 + (size_t)r * (D_FEAT / 4) + lane;
        const float4 v0 = __ldcs(base + 0 * 32);
        const float4 v1 = __ldcs(base + 1 * 32);
        const float4 v2 = __ldcs(base + 2 * 32);
        const float4 v3 = __ldcs(base + 3 * 32);
        const float4 v4 = __ldcs(base + 4 * 32);
        const float4 v5 = __ldcs(base + 5 * 32);
        const float4 v6 = __ldcs(base + 6 * 32);
        const float4 v7 = __ldcs(base + 7 * 32);

        if (sB.w == cur) {
            // sorted ids: last == cur  =>  all 8 == cur
            float4 t0s = f4add(f4add(v0, v1), f4add(v2, v3));
            float4 t1s = f4add(f4add(v4, v5), f4add(v6, v7));
            acc = f4add(acc, f4add(t0s, t1s));
        } else {
            // cold path: segment boundary inside this batch
            int s[8] = {sA.x, sA.y, sA.z, sA.w, sB.x, sB.y, sB.z, sB.w};
            float4 v[8] = {v0, v1, v2, v3, v4, v5, v6, v7};
            #pragma unroll
            for (int i = 0; i < 8; i++) {
                if (s[i] != cur) {
                    flush_acc(out, cur, lane, acc);
                    acc = make_float4(0.f, 0.f, 0.f, 0.f);
                    cur = s[i];
                }
                acc = f4add(acc, v[i]);
            }
        }
    }
    // ---------- scalar tail (only last chain, if n_rows % 8 != 0) ----------
    for (; r < r1; ++r) {
        int s = __ldcs(seg + r);
        float4 v = __ldcs(feat4 + (size_t)r * (D_FEAT / 4) + lane);
        if (s != cur) {
            flush_acc(out, cur, lane, acc);
            acc = make_float4(0.f, 0.f, 0.f, 0.f);
            cur = s;
        }
        acc = f4add(acc, v);
    }

    flush_acc(out, cur, lane, acc);
}

extern "C" void kernel_launch(void* const* d_in, const int* in_sizes, int n_in,
                              void* d_out, int out_size) {
    const float* feat = (const float*)d_in[0];
    const int* seg = (const int*)d_in[1];
    float* out = (float*)d_out;

    const int n_rows = in_sizes[0] / D_FEAT;  // 1,000,000
    const int n4 = out_size / 4;              // 131072

    zero_out_kernel<<<(n4 + 255) / 256, 256>>>((float4*)out, n4);
    segsum_kernel<<<GRID_BLOCKS, THREADS>>>((const float4*)feat, seg, out, n_rows);
}

// round 10
// speedup vs baseline: 1.0608x; 1.0004x over previous
#include <cuda_runtime.h>
#include <cuda_bf16.h>
#include <cstddef>

// Sorted segment-sum: feat[1e6, 128] fp32 -> out[4096, 128] fp32.
// R3 architecture (best so far): static dispatch, 2368 blocks = 4 waves of
// 4 resident blocks/SM, one warp per contiguous chain of 8-row tiles,
// balanced split. NEW in R9: GUIDED two-tier chain sizing - blocks execute
// roughly in index order, so the first 3 waves (14208 chains) take 7/8 of
// the tiles (~61-row chains) and the LAST wave (4736 chains) takes 1/8
// (~26-row chains). The final wave is the only one whose completion spread
// is exposed as chip idle; 2.4x shorter chains shrink that tail ~2.4x.
// Hot loop: 8 rows/iter, branch-free front-batched streaming loads
// (2x int4 seg + 8x float4 feat => MLP ~10/warp). Sortedness: last id in
// batch == cur => whole batch == cur. Flushes are atomicAdds into the 2MB
// L2-resident output - negligible DRAM traffic.

#define WARPS_PER_BLOCK 8
#define THREADS (WARPS_PER_BLOCK * 32)
#define GRID_BLOCKS 2368                        // 4 waves x 592
#define N_CHAINS ((long)GRID_BLOCKS * WARPS_PER_BLOCK)  // 18944
#define T1_CHAINS 14208                         // first 3 waves
#define T2_CHAINS 4736                          // last wave
#define D_FEAT 128

__global__ void zero_out_kernel(float4* __restrict__ out, int n4) {
    int i = blockIdx.x * blockDim.x + threadIdx.x;
    if (i < n4) out[i] = make_float4(0.f, 0.f, 0.f, 0.f);
}

__device__ __forceinline__ float4 f4add(float4 a, float4 b) {
    return make_float4(a.x + b.x, a.y + b.y, a.z + b.z, a.w + b.w);
}

__device__ __forceinline__ void flush_acc(float* __restrict__ out, int cur,
                                          int lane, float4 acc) {
    float* dst = out + (size_t)cur * D_FEAT + lane * 4;
    atomicAdd(dst + 0, acc.x);
    atomicAdd(dst + 1, acc.y);
    atomicAdd(dst + 2, acc.z);
    atomicAdd(dst + 3, acc.w);
}

__global__ __launch_bounds__(THREADS, 4)
void segsum_kernel(const float4* __restrict__ feat4,
                   const int* __restrict__ seg,
                   float* __restrict__ out,
                   int n_rows) {
    const int warp = threadIdx.x >> 5;
    const int lane = threadIdx.x & 31;
    const long chain = (long)blockIdx.x * WARPS_PER_BLOCK + warp;

    const long n_tiles = n_rows >> 3;            // full 8-row tiles
    const long tiles_t1 = (n_tiles * 7) >> 3;    // 7/8 to the first 3 waves

    // Guided two-tier balanced split.
    long t0, t1;
    if (chain < T1_CHAINS) {
        t0 = (chain * tiles_t1) / T1_CHAINS;
        t1 = ((chain + 1) * tiles_t1) / T1_CHAINS;
    } else {
        const long c2 = chain - T1_CHAINS;
        const long tiles_t2 = n_tiles - tiles_t1;
        t0 = tiles_t1 + (c2 * tiles_t2) / T2_CHAINS;
        t1 = tiles_t1 + ((c2 + 1) * tiles_t2) / T2_CHAINS;
    }
    long r0 = t0 << 3;
    long r1 = t1 << 3;
    if (chain == N_CHAINS - 1) r1 = n_rows;      // remainder rows
    if (r0 >= r1) return;

    float4 acc = make_float4(0.f, 0.f, 0.f, 0.f);
    int cur = __ldcs(seg + r0);

    long r = r0;
    // ---------- hot loop: branch-free loads, 8 rows / iter ----------
    for (; r + 8 <= r1; r += 8) {
        const int4 sA = __ldcs(reinterpret_cast<const int4*>(seg + r));
        const int4 sB = __ldcs(reinterpret_cast<const int4*>(seg + r + 4));
        const float4* base = feat4 + (size_t)r * (D_FEAT / 4) + lane;
        const float4 v0 = __ldcs(base + 0 * 32);
        const float4 v1 = __ldcs(base + 1 * 32);
        const float4 v2 = __ldcs(base + 2 * 32);
        const float4 v3 = __ldcs(base + 3 * 32);
        const float4 v4 = __ldcs(base + 4 * 32);
        const float4 v5 = __ldcs(base + 5 * 32);
        const float4 v6 = __ldcs(base + 6 * 32);
        const float4 v7 = __ldcs(base + 7 * 32);

        if (sB.w == cur) {
            // sorted ids: last == cur  =>  all 8 == cur
            float4 t0s = f4add(f4add(v0, v1), f4add(v2, v3));
            float4 t1s = f4add(f4add(v4, v5), f4add(v6, v7));
            acc = f4add(acc, f4add(t0s, t1s));
        } else {
            // cold path: segment boundary inside this batch
            int s[8] = {sA.x, sA.y, sA.z, sA.w, sB.x, sB.y, sB.z, sB.w};
            float4 v[8] = {v0, v1, v2, v3, v4, v5, v6, v7};
            #pragma unroll
            for (int i = 0; i < 8; i++) {
                if (s[i] != cur) {
                    flush_acc(out, cur, lane, acc);
                    acc = make_float4(0.f, 0.f, 0.f, 0.f);
                    cur = s[i];
                }
                acc = f4add(acc, v[i]);
            }
        }
    }
    // ---------- scalar tail (only last chain, if n_rows % 8 != 0) ----------
    for (; r < r1; ++r) {
        int s = __ldcs(seg + r);
        float4 v = __ldcs(feat4 + (size_t)r * (D_FEAT / 4) + lane);
        if (s != cur) {
            flush_acc(out, cur, lane, acc);
            acc = make_float4(0.f, 0.f, 0.f, 0.f);
            cur = s;
        }
        acc = f4add(acc, v);
    }

    flush_acc(out, cur, lane, acc);
}

extern "C" void kernel_launch(void* const* d_in, const int* in_sizes, int n_in,
                              void* d_out, int out_size) {
    const float* feat = (const float*)d_in[0];
    const int* seg = (const int*)d_in[1];
    float* out = (float*)d_out;

    const int n_rows = in_sizes[0] / D_FEAT;  // 1,000,000
    const int n4 = out_size / 4;              // 131072

    zero_out_kernel<<<(n4 + 255) / 256, 256>>>((float4*)out, n4);
    segsum_kernel<<<GRID_BLOCKS, THREADS>>>((const float4*)feat, seg, out, n_rows);
}